// round 3
// baseline (speedup 1.0000x reference)
#include <cuda_runtime.h>
#include <math.h>

#define DV    10000      // vocab rows
#define NP1   10001      // D+1 (softmax width)
#define HDIM  1024       // hidden
#define MROWS 4096       // B*L

// ---------------------------------------------------------------------------
// Kernel 1: logits[m][n] = sum_k desc[m][k] * fullvocab[n][k]   (NT sgemm)
//   fullvocab[n] = vocab[n] for n<DV, default_embedding for n==DV
//   C written to the similarity region of d_out (ldc = 10001)
// Tiling: BM=128, BN=128, BK=16, 256 threads, 8x8 per thread.
// ---------------------------------------------------------------------------
__global__ __launch_bounds__(256) void gemm_logits(
    const float* __restrict__ A,   // desc  4096 x 1024
    const float* __restrict__ V,   // vocab 10000 x 1024
    const float* __restrict__ E,   // default 1024
    float* __restrict__ C)         // logits 4096 x 10001
{
    const int BM = 128, BN = 128, BK = 16;
    __shared__ float As[BK][BM];
    __shared__ float Bs[BK][BN];

    const int tid  = threadIdx.x;
    const int bm   = blockIdx.y * BM;
    const int bn   = blockIdx.x * BN;

    const int lrow  = tid >> 2;         // 0..63
    const int lcol4 = (tid & 3) * 4;    // 0,4,8,12

    const int tr = tid >> 4;            // 0..15
    const int tc = tid & 15;            // 0..15

    float acc[8][8];
    #pragma unroll
    for (int i = 0; i < 8; i++)
        #pragma unroll
        for (int j = 0; j < 8; j++) acc[i][j] = 0.f;

    for (int k0 = 0; k0 < HDIM; k0 += BK) {
        // --- A tile: rows bm+lrow, bm+lrow+64, cols k0+lcol4..+3 (transpose to As[k][m])
        #pragma unroll
        for (int r = 0; r < 2; r++) {
            int m = lrow + r * 64;
            float4 a = *(const float4*)(A + (size_t)(bm + m) * HDIM + k0 + lcol4);
            As[lcol4 + 0][m] = a.x;
            As[lcol4 + 1][m] = a.y;
            As[lcol4 + 2][m] = a.z;
            As[lcol4 + 3][m] = a.w;
        }
        // --- B tile: rows bn+lrow(+64) of fullvocab, cols k0+lcol4..+3
        #pragma unroll
        for (int r = 0; r < 2; r++) {
            int n  = lrow + r * 64;
            int gn = bn + n;
            float4 b;
            if (gn < DV)        b = *(const float4*)(V + (size_t)gn * HDIM + k0 + lcol4);
            else if (gn == DV)  b = *(const float4*)(E + k0 + lcol4);
            else                b = make_float4(0.f, 0.f, 0.f, 0.f);
            Bs[lcol4 + 0][n] = b.x;
            Bs[lcol4 + 1][n] = b.y;
            Bs[lcol4 + 2][n] = b.z;
            Bs[lcol4 + 3][n] = b.w;
        }
        __syncthreads();

        #pragma unroll
        for (int k = 0; k < BK; k++) {
            float ra[8], rb[8];
            float4 a0 = *(const float4*)&As[k][tr * 8];
            float4 a1 = *(const float4*)&As[k][tr * 8 + 4];
            float4 b0 = *(const float4*)&Bs[k][tc * 8];
            float4 b1 = *(const float4*)&Bs[k][tc * 8 + 4];
            ra[0]=a0.x; ra[1]=a0.y; ra[2]=a0.z; ra[3]=a0.w;
            ra[4]=a1.x; ra[5]=a1.y; ra[6]=a1.z; ra[7]=a1.w;
            rb[0]=b0.x; rb[1]=b0.y; rb[2]=b0.z; rb[3]=b0.w;
            rb[4]=b1.x; rb[5]=b1.y; rb[6]=b1.z; rb[7]=b1.w;
            #pragma unroll
            for (int i = 0; i < 8; i++)
                #pragma unroll
                for (int j = 0; j < 8; j++)
                    acc[i][j] = fmaf(ra[i], rb[j], acc[i][j]);
        }
        __syncthreads();
    }

    // store (guard n < 10001)
    #pragma unroll
    for (int i = 0; i < 8; i++) {
        int m = bm + tr * 8 + i;
        #pragma unroll
        for (int j = 0; j < 8; j++) {
            int n = bn + tc * 8 + j;
            if (n < NP1) C[(size_t)m * NP1 + n] = acc[i][j];
        }
    }
}

// ---------------------------------------------------------------------------
// Kernel 2: in-place row softmax over NP1 entries. One block per row.
// Online max/sum in one read pass, then one read+write pass.
// ---------------------------------------------------------------------------
__global__ __launch_bounds__(256) void softmax_rows(float* __restrict__ P)
{
    const int row = blockIdx.x;
    float* p = P + (size_t)row * NP1;

    float lm = -3.402823466e+38f;
    float ls = 0.f;
    for (int i = threadIdx.x; i < NP1; i += 256) {
        float x = p[i];
        if (x > lm) {
            ls = ls * expf(lm - x) + 1.f;
            lm = x;
        } else {
            ls += expf(x - lm);
        }
    }

    __shared__ float sm[256];
    __shared__ float ss[256];
    sm[threadIdx.x] = lm;
    ss[threadIdx.x] = ls;
    __syncthreads();

    for (int stride = 128; stride > 0; stride >>= 1) {
        if (threadIdx.x < stride) {
            float m1 = sm[threadIdx.x],          s1 = ss[threadIdx.x];
            float m2 = sm[threadIdx.x + stride], s2 = ss[threadIdx.x + stride];
            float M = fmaxf(m1, m2);
            sm[threadIdx.x] = M;
            ss[threadIdx.x] = s1 * expf(m1 - M) + s2 * expf(m2 - M);
        }
        __syncthreads();
    }

    const float M    = sm[0];
    const float rinv = 1.f / ss[0];

    for (int i = threadIdx.x; i < NP1; i += 256) {
        p[i] = expf(p[i] - M) * rinv;
    }
}

// ---------------------------------------------------------------------------
// Kernel 3: concept[m][n] = sum_{k<DV} sim[m][k]*vocab[k][n]
//                           + sim[m][DV]*desc[m][n]              (NN sgemm)
// A = sim (lda=10001, scalar loads — lda not /4), B = vocab (K x N row-major)
// ---------------------------------------------------------------------------
__global__ __launch_bounds__(256) void gemm_concept(
    const float* __restrict__ S,    // sim  4096 x 10001
    const float* __restrict__ V,    // vocab 10000 x 1024
    const float* __restrict__ Dsc,  // desc 4096 x 1024
    float* __restrict__ O)          // concept 4096 x 1024
{
    const int BM = 128, BN = 128, BK = 16;
    __shared__ float As[BK][BM];
    __shared__ float Bs[BK][BN];

    const int tid = threadIdx.x;
    const int bm  = blockIdx.y * BM;
    const int bn  = blockIdx.x * BN;

    const int tr = tid >> 4;
    const int tc = tid & 15;

    // A-load mapping: thread -> (m = tid>>4 + r*16, k = tid&15), 8 reps
    const int am = tid >> 4;      // 0..15
    const int ak = tid & 15;      // 0..15
    // B-load mapping: thread -> (k = tid>>5 + r*8, n4 = (tid&31)*4), 2 reps
    const int bk  = tid >> 5;     // 0..7
    const int bn4 = (tid & 31) * 4;

    float acc[8][8];
    #pragma unroll
    for (int i = 0; i < 8; i++)
        #pragma unroll
        for (int j = 0; j < 8; j++) acc[i][j] = 0.f;

    for (int k0 = 0; k0 < DV; k0 += BK) {
        // A tile (scalar, lda = 10001)
        #pragma unroll
        for (int r = 0; r < 8; r++) {
            int m = am + r * 16;
            As[ak][m] = S[(size_t)(bm + m) * NP1 + k0 + ak];
        }
        // B tile (float4 along n)
        #pragma unroll
        for (int r = 0; r < 2; r++) {
            int k = bk + r * 8;
            float4 b = *(const float4*)(V + (size_t)(k0 + k) * HDIM + bn + bn4);
            *(float4*)&Bs[k][bn4] = b;
        }
        __syncthreads();

        #pragma unroll
        for (int k = 0; k < BK; k++) {
            float ra[8], rb[8];
            float4 a0 = *(const float4*)&As[k][tr * 8];
            float4 a1 = *(const float4*)&As[k][tr * 8 + 4];
            float4 b0 = *(const float4*)&Bs[k][tc * 8];
            float4 b1 = *(const float4*)&Bs[k][tc * 8 + 4];
            ra[0]=a0.x; ra[1]=a0.y; ra[2]=a0.z; ra[3]=a0.w;
            ra[4]=a1.x; ra[5]=a1.y; ra[6]=a1.z; ra[7]=a1.w;
            rb[0]=b0.x; rb[1]=b0.y; rb[2]=b0.z; rb[3]=b0.w;
            rb[4]=b1.x; rb[5]=b1.y; rb[6]=b1.z; rb[7]=b1.w;
            #pragma unroll
            for (int i = 0; i < 8; i++)
                #pragma unroll
                for (int j = 0; j < 8; j++)
                    acc[i][j] = fmaf(ra[i], rb[j], acc[i][j]);
        }
        __syncthreads();
    }

    // epilogue: + sim[m][DV] * desc[m][n], vectorized store
    #pragma unroll
    for (int i = 0; i < 8; i++) {
        int m = bm + tr * 8 + i;
        float w = S[(size_t)m * NP1 + DV];
        #pragma unroll
        for (int j4 = 0; j4 < 2; j4++) {
            int n = bn + tc * 8 + j4 * 4;
            float4 d = *(const float4*)(Dsc + (size_t)m * HDIM + n);
            float4 o;
            o.x = acc[i][j4*4+0] + w * d.x;
            o.y = acc[i][j4*4+1] + w * d.y;
            o.z = acc[i][j4*4+2] + w * d.z;
            o.w = acc[i][j4*4+3] + w * d.w;
            *(float4*)(O + (size_t)m * HDIM + n) = o;
        }
    }
}

// ---------------------------------------------------------------------------
extern "C" void kernel_launch(void* const* d_in, const int* in_sizes, int n_in,
                              void* d_out, int out_size)
{
    const float* vocab = (const float*)d_in[0];   // 10000 x 1024
    const float* desc  = (const float*)d_in[1];   // 8 x 512 x 1024
    const float* defe  = (const float*)d_in[2];   // 1024

    float* concept = (float*)d_out;                       // 4096 x 1024
    float* sim     = concept + (size_t)MROWS * HDIM;      // 4096 x 10001

    // 1) logits -> sim region
    {
        dim3 grid((NP1 + 127) / 128, MROWS / 128);   // 79 x 32
        gemm_logits<<<grid, 256>>>(desc, vocab, defe, sim);
    }
    // 2) softmax in place
    {
        softmax_rows<<<MROWS, 256>>>(sim);
    }
    // 3) blend
    {
        dim3 grid(HDIM / 128, MROWS / 128);          // 8 x 32
        gemm_concept<<<grid, 256>>>(sim, vocab, desc, concept);
    }
}

// round 6
// speedup vs baseline: 2.4441x; 2.4441x over previous
#include <cuda_runtime.h>
#include <cuda_bf16.h>
#include <stdint.h>
#include <math.h>

#define DV    10000      // vocab rows
#define NP1   10001      // D+1 (softmax width)
#define HDIM  1024       // hidden
#define MROWS 4096       // B*L
#define NPAD1 10112      // 79*128   (GEMM1 N padding, vocab rows)
#define KPAD2 10048      // 314*32   (GEMM2 K padding)

// ---------------------------------------------------------------------------
// Static device scratch (allocation-free rule: __device__ globals)
// NOTE: host code must use cudaGetSymbolAddress — passing these identifiers
// directly as kernel args from host yields the host shadow (Round-5 bug).
// ---------------------------------------------------------------------------
__device__ __align__(256) __nv_bfloat16 g_descH[(size_t)MROWS * HDIM];
__device__ __align__(256) __nv_bfloat16 g_descL[(size_t)MROWS * HDIM];
__device__ __align__(256) __nv_bfloat16 g_vocH [(size_t)NPAD1 * HDIM];
__device__ __align__(256) __nv_bfloat16 g_vocL [(size_t)NPAD1 * HDIM];
__device__ __align__(256) __nv_bfloat16 g_vocTH[(size_t)HDIM * KPAD2];
__device__ __align__(256) __nv_bfloat16 g_vocTL[(size_t)HDIM * KPAD2];
__device__ __align__(256) __nv_bfloat16 g_simH [(size_t)MROWS * KPAD2];
__device__ __align__(256) __nv_bfloat16 g_simL [(size_t)MROWS * KPAD2];

// ---------------------------------------------------------------------------
// plain-PTX helpers (sm_80+ only: cp.async, ldmatrix, mma.sync)
// ---------------------------------------------------------------------------
__device__ __forceinline__ uint32_t smem_u32(const void* p) {
    uint32_t a;
    asm("{ .reg .u64 t; cvta.to.shared.u64 t, %1; cvt.u32.u64 %0, t; }"
        : "=r"(a) : "l"(p));
    return a;
}

__device__ __forceinline__ void cp_async16(uint32_t dst, const void* src) {
    asm volatile("cp.async.cg.shared.global [%0], [%1], 16;"
                 :: "r"(dst), "l"(src));
}
__device__ __forceinline__ void cp_commit() {
    asm volatile("cp.async.commit_group;");
}
__device__ __forceinline__ void cp_wait1() {
    asm volatile("cp.async.wait_group 1;");
}

__device__ __forceinline__ void ldsm4(uint32_t* r, uint32_t addr) {
    asm volatile("ldmatrix.sync.aligned.m8n8.x4.shared.b16 {%0,%1,%2,%3}, [%4];"
                 : "=r"(r[0]), "=r"(r[1]), "=r"(r[2]), "=r"(r[3])
                 : "r"(addr));
}

__device__ __forceinline__ void mma16816(float* c, const uint32_t* a,
                                         uint32_t b0, uint32_t b1) {
    asm volatile(
        "mma.sync.aligned.m16n8k16.row.col.f32.bf16.bf16.f32 "
        "{%0,%1,%2,%3}, {%4,%5,%6,%7}, {%8,%9}, {%0,%1,%2,%3};"
        : "+f"(c[0]), "+f"(c[1]), "+f"(c[2]), "+f"(c[3])
        : "r"(a[0]), "r"(a[1]), "r"(a[2]), "r"(a[3]), "r"(b0), "r"(b1));
}

// ---------------------------------------------------------------------------
// Conversion kernels: fp32 -> bf16 hi/lo splits
// ---------------------------------------------------------------------------
__global__ __launch_bounds__(256) void k_split_desc(const float* __restrict__ D) {
    long i = (long)blockIdx.x * 256 + threadIdx.x;
    if (i >= (long)MROWS * HDIM) return;
    float x = D[i];
    __nv_bfloat16 h = __float2bfloat16(x);
    g_descH[i] = h;
    g_descL[i] = __float2bfloat16(x - __bfloat162float(h));
}

__global__ __launch_bounds__(256) void k_split_vocab(const float* __restrict__ V,
                                                     const float* __restrict__ E) {
    long i = (long)blockIdx.x * 256 + threadIdx.x;
    if (i >= (long)NPAD1 * HDIM) return;
    long row = i >> 10;
    int  col = (int)(i & 1023);
    float x;
    if (row < DV)       x = V[i];
    else if (row == DV) x = E[col];
    else                x = 0.f;
    __nv_bfloat16 h = __float2bfloat16(x);
    g_vocH[i] = h;
    g_vocL[i] = __float2bfloat16(x - __bfloat162float(h));
}

// vocabT[n][k] = vocab[k][n], bf16 hi/lo, K padded to KPAD2 with zeros
__global__ __launch_bounds__(256) void k_vocabT(const float* __restrict__ V) {
    __shared__ float t[32][33];
    int k0 = blockIdx.x * 32;
    int n0 = blockIdx.y * 32;
    #pragma unroll
    for (int r = 0; r < 32; r += 8) {
        int k = k0 + threadIdx.y + r;
        t[threadIdx.y + r][threadIdx.x] =
            (k < DV) ? V[(long)k * HDIM + n0 + threadIdx.x] : 0.f;
    }
    __syncthreads();
    #pragma unroll
    for (int r = 0; r < 32; r += 8) {
        int n = n0 + threadIdx.y + r;
        int k = k0 + threadIdx.x;
        float x = t[threadIdx.x][threadIdx.y + r];
        __nv_bfloat16 h = __float2bfloat16(x);
        g_vocTH[(long)n * KPAD2 + k] = h;
        g_vocTL[(long)n * KPAD2 + k] = __float2bfloat16(x - __bfloat162float(h));
    }
}

// ---------------------------------------------------------------------------
// Softmax: fp32 in place + bf16 hi/lo split of sim[:, 0:DV] (default slot and
// K padding zeroed in the bf16 arrays — default slot fused in GEMM2 epilogue)
// ---------------------------------------------------------------------------
__global__ __launch_bounds__(256) void softmax_rows(float* __restrict__ P) {
    const int row = blockIdx.x;
    float* p = P + (size_t)row * NP1;

    float lm = -3.402823466e+38f;
    float ls = 0.f;
    for (int i = threadIdx.x; i < NP1; i += 256) {
        float x = p[i];
        if (x > lm) { ls = ls * expf(lm - x) + 1.f; lm = x; }
        else        { ls += expf(x - lm); }
    }

    __shared__ float sm[256];
    __shared__ float ss[256];
    sm[threadIdx.x] = lm;
    ss[threadIdx.x] = ls;
    __syncthreads();
    for (int stride = 128; stride > 0; stride >>= 1) {
        if (threadIdx.x < stride) {
            float m1 = sm[threadIdx.x],          s1 = ss[threadIdx.x];
            float m2 = sm[threadIdx.x + stride], s2 = ss[threadIdx.x + stride];
            float M = fmaxf(m1, m2);
            sm[threadIdx.x] = M;
            ss[threadIdx.x] = s1 * expf(m1 - M) + s2 * expf(m2 - M);
        }
        __syncthreads();
    }
    const float M    = sm[0];
    const float rinv = 1.f / ss[0];

    __nv_bfloat16* sh = g_simH + (long)row * KPAD2;
    __nv_bfloat16* sl = g_simL + (long)row * KPAD2;
    for (int i = threadIdx.x; i < NP1; i += 256) {
        float pv = expf(p[i] - M) * rinv;
        p[i] = pv;
        if (i < DV) {
            __nv_bfloat16 h = __float2bfloat16(pv);
            sh[i] = h;
            sl[i] = __float2bfloat16(pv - __bfloat162float(h));
        }
    }
    for (int i = DV + threadIdx.x; i < KPAD2; i += 256) {
        sh[i] = __float2bfloat16(0.f);
        sl[i] = __float2bfloat16(0.f);
    }
}

// ---------------------------------------------------------------------------
// mma.sync bf16x3 GEMM:  D[128,128] f32 = A[128,K] * B[128,K]^T
// A ~ Ah+Al, B ~ Bh+Bl; accumulate Ah*Bh + Ah*Bl + Al*Bh (fp32 accum).
// 256 threads, warp grid 2(m) x 4(n), warp tile 64x32, BK=32, 3-stage cp.async.
// Smem per stage: 4 tiles (Ah,Al,Bh,Bl), 128 rows x 64B data, 80B padded row.
// MODE 0: logits epilogue (ldc=NP1, column guard)
// MODE 1: blend epilogue  (C = D + sim[:,DV]*desc, ldc=HDIM)
// ---------------------------------------------------------------------------
#define AREA  10240              // one tile (128 rows * 80B)
#define STAGE 40960              // 4 tiles
#define GEMM_SMEM_BYTES (3 * STAGE)

__device__ __forceinline__ void stage_load(
    uint32_t stb,
    const __nv_bfloat16* __restrict__ Ah, const __nv_bfloat16* __restrict__ Al,
    long bm, long lda,
    const __nv_bfloat16* __restrict__ Bh, const __nv_bfloat16* __restrict__ Bl,
    long bn, long ldb,
    int k0, int tid)
{
    const int seg = tid & 3;
    #pragma unroll
    for (int r = 0; r < 8; r++) {
        const int arr = r >> 1;                       // 0..3: Ah, Al, Bh, Bl
        const int row = (r & 1) * 64 + (tid >> 2);    // 0..127
        const __nv_bfloat16* src;
        if (arr == 0)      src = Ah + (bm + row) * lda;
        else if (arr == 1) src = Al + (bm + row) * lda;
        else if (arr == 2) src = Bh + (bn + row) * ldb;
        else               src = Bl + (bn + row) * ldb;
        src += k0 + seg * 8;
        uint32_t dst = stb + (uint32_t)arr * AREA + (uint32_t)row * 80 + (uint32_t)seg * 16;
        cp_async16(dst, src);
    }
}

template <int MODE>
__global__ __launch_bounds__(256, 1)
void gemm_bf16x3(const __nv_bfloat16* __restrict__ Ah,
                 const __nv_bfloat16* __restrict__ Al, long lda,
                 const __nv_bfloat16* __restrict__ Bh,
                 const __nv_bfloat16* __restrict__ Bl, long ldb,
                 int KTOT,
                 float* __restrict__ C,
                 const float* __restrict__ simF,
                 const float* __restrict__ descF)
{
    extern __shared__ char smem[];
    const int tid  = threadIdx.x;
    const int lane = tid & 31;
    const int wid  = tid >> 5;
    const int wm   = wid >> 2;      // 0..1
    const int wn   = wid & 3;       // 0..3
    const uint32_t sb = smem_u32(smem);

    const long bm = (long)blockIdx.y * 128;
    const long bn = (long)blockIdx.x * 128;

    // ldmatrix per-lane addressing: tiles ordered (r0,k0),(r8,k0),(r0,k8),(r8,k8)
    const int lrow = ((lane >> 3) & 1) * 8 + (lane & 7);
    const int lseg = lane >> 4;     // 0..1 (16B column segment within k16)

    float acc[4][4][4];
    #pragma unroll
    for (int i = 0; i < 4; i++)
        #pragma unroll
        for (int j = 0; j < 4; j++)
            #pragma unroll
            for (int q = 0; q < 4; q++) acc[i][j][q] = 0.f;

    const int NC = KTOT >> 5;

    stage_load(sb + 0 * STAGE, Ah, Al, bm, lda, Bh, Bl, bn, ldb, 0, tid);
    cp_commit();
    stage_load(sb + 1 * STAGE, Ah, Al, bm, lda, Bh, Bl, bn, ldb, 32, tid);
    cp_commit();

    int cs = 0;  // current stage index (c % 3)
    for (int c = 0; c < NC; ++c) {
        cp_wait1();
        __syncthreads();

        if (c + 2 < NC) {
            int ns = cs + 2; if (ns >= 3) ns -= 3;
            stage_load(sb + (uint32_t)ns * STAGE, Ah, Al, bm, lda, Bh, Bl, bn, ldb,
                       (c + 2) << 5, tid);
        }
        cp_commit();

        const uint32_t stb = sb + (uint32_t)cs * STAGE;
        #pragma unroll
        for (int kh = 0; kh < 2; kh++) {
            uint32_t afH[4][4], afL[4][4];
            #pragma unroll
            for (int mt = 0; mt < 4; mt++) {
                uint32_t ra = stb + (uint32_t)((wm * 64 + mt * 16 + lrow) * 80
                                               + kh * 32 + lseg * 16);
                ldsm4(afH[mt], ra);
                ldsm4(afL[mt], ra + AREA);
            }
            uint32_t bfH[2][4], bfL[2][4];
            #pragma unroll
            for (int nt = 0; nt < 2; nt++) {
                uint32_t rb = stb + 2u * AREA
                            + (uint32_t)((wn * 32 + nt * 16 + lrow) * 80
                                         + kh * 32 + lseg * 16);
                ldsm4(bfH[nt], rb);
                ldsm4(bfL[nt], rb + AREA);
            }
            #pragma unroll
            for (int mt = 0; mt < 4; mt++) {
                #pragma unroll
                for (int nb = 0; nb < 4; nb++) {
                    const int nt = nb >> 1, hs = nb & 1;
                    mma16816(acc[mt][nb], afH[mt], bfH[nt][hs], bfH[nt][hs + 2]);
                    mma16816(acc[mt][nb], afH[mt], bfL[nt][hs], bfL[nt][hs + 2]);
                    mma16816(acc[mt][nb], afL[mt], bfH[nt][hs], bfH[nt][hs + 2]);
                }
            }
        }
        __syncthreads();
        ++cs; if (cs == 3) cs = 0;
    }

    // ---- epilogue: direct stores from mma C fragments
    const int group = lane >> 2;
    const int q2    = (lane & 3) * 2;
    #pragma unroll
    for (int mt = 0; mt < 4; mt++) {
        long m0 = bm + wm * 64 + mt * 16 + group;
        long m1 = m0 + 8;
        float w0 = 0.f, w1 = 0.f;
        if (MODE == 1) {
            w0 = simF[m0 * NP1 + DV];
            w1 = simF[m1 * NP1 + DV];
        }
        #pragma unroll
        for (int nb = 0; nb < 4; nb++) {
            long n = bn + wn * 32 + nb * 8 + q2;
            const float* cc = acc[mt][nb];
            if (MODE == 0) {
                if (n < NP1)     C[m0 * NP1 + n]     = cc[0];
                if (n + 1 < NP1) C[m0 * NP1 + n + 1] = cc[1];
                if (n < NP1)     C[m1 * NP1 + n]     = cc[2];
                if (n + 1 < NP1) C[m1 * NP1 + n + 1] = cc[3];
            } else {
                C[m0 * HDIM + n]     = cc[0] + w0 * descF[m0 * HDIM + n];
                C[m0 * HDIM + n + 1] = cc[1] + w0 * descF[m0 * HDIM + n + 1];
                C[m1 * HDIM + n]     = cc[2] + w1 * descF[m1 * HDIM + n];
                C[m1 * HDIM + n + 1] = cc[3] + w1 * descF[m1 * HDIM + n + 1];
            }
        }
    }
}

// ---------------------------------------------------------------------------
extern "C" void kernel_launch(void* const* d_in, const int* in_sizes, int n_in,
                              void* d_out, int out_size)
{
    const float* vocab = (const float*)d_in[0];   // 10000 x 1024
    const float* desc  = (const float*)d_in[1];   // 8 x 512 x 1024
    const float* defe  = (const float*)d_in[2];   // 1024

    float* concept = (float*)d_out;                       // 4096 x 1024
    float* sim     = concept + (size_t)MROWS * HDIM;      // 4096 x 10001

    // Real device addresses of the __device__ scratch symbols (Round-5 fix:
    // passing the symbols directly gives the host shadow, which ATS serves
    // as zeros on GB300).
    __nv_bfloat16 *descH, *descL, *vocH, *vocL, *vocTH, *vocTL, *simH, *simL;
    cudaGetSymbolAddress((void**)&descH, g_descH);
    cudaGetSymbolAddress((void**)&descL, g_descL);
    cudaGetSymbolAddress((void**)&vocH,  g_vocH);
    cudaGetSymbolAddress((void**)&vocL,  g_vocL);
    cudaGetSymbolAddress((void**)&vocTH, g_vocTH);
    cudaGetSymbolAddress((void**)&vocTL, g_vocTL);
    cudaGetSymbolAddress((void**)&simH,  g_simH);
    cudaGetSymbolAddress((void**)&simL,  g_simL);

    cudaFuncSetAttribute(gemm_bf16x3<0>, cudaFuncAttributeMaxDynamicSharedMemorySize,
                         GEMM_SMEM_BYTES);
    cudaFuncSetAttribute(gemm_bf16x3<1>, cudaFuncAttributeMaxDynamicSharedMemorySize,
                         GEMM_SMEM_BYTES);

    // 0) fp32 -> bf16 hi/lo conversions
    {
        long n1 = (long)MROWS * HDIM;
        k_split_desc<<<(unsigned)((n1 + 255) / 256), 256>>>(desc);
        long n2 = (long)NPAD1 * HDIM;
        k_split_vocab<<<(unsigned)((n2 + 255) / 256), 256>>>(vocab, defe);
        dim3 tg(KPAD2 / 32, HDIM / 32);
        k_vocabT<<<tg, dim3(32, 8)>>>(vocab);
    }
    // 1) logits = desc @ fullvocab^T  -> sim region (fp32)
    {
        dim3 grid(NPAD1 / 128, MROWS / 128);   // 79 x 32
        gemm_bf16x3<0><<<grid, 256, GEMM_SMEM_BYTES>>>(
            descH, descL, HDIM,
            vocH,  vocL,  HDIM,
            HDIM, sim, nullptr, nullptr);
    }
    // 2) softmax in place + bf16 hi/lo sim
    softmax_rows<<<MROWS, 256>>>(sim);
    // 3) concept = sim[:, :DV] @ vocab + sim[:, DV] * desc
    {
        dim3 grid(HDIM / 128, MROWS / 128);    // 8 x 32
        gemm_bf16x3<1><<<grid, 256, GEMM_SMEM_BYTES>>>(
            simH,  simL,  KPAD2,
            vocTH, vocTL, KPAD2,
            KPAD2, concept, sim, desc);
    }
}

// round 7
// speedup vs baseline: 2.6442x; 1.0819x over previous
#include <cuda_runtime.h>
#include <cuda_bf16.h>
#include <stdint.h>
#include <math.h>

#define DV    10000      // vocab rows
#define NP1   10001      // D+1 (softmax width)
#define HDIM  1024      // hidden
#define MROWS 4096      // B*L
#define NPAD1 10112      // 79*128   (GEMM1 N padding, vocab rows)
#define KPAD2 10048      // 314*32   (GEMM2 K padding)

// ---------------------------------------------------------------------------
// Static device scratch (allocation-free rule: __device__ globals)
// NOTE: host code must use cudaGetSymbolAddress — passing these identifiers
// directly as kernel args from host yields the host shadow (Round-5 bug).
// ---------------------------------------------------------------------------
__device__ __align__(256) __nv_bfloat16 g_descH[(size_t)MROWS * HDIM];
__device__ __align__(256) __nv_bfloat16 g_descL[(size_t)MROWS * HDIM];
__device__ __align__(256) __nv_bfloat16 g_vocH [(size_t)NPAD1 * HDIM];
__device__ __align__(256) __nv_bfloat16 g_vocL [(size_t)NPAD1 * HDIM];
__device__ __align__(256) __nv_bfloat16 g_vocTH[(size_t)HDIM * KPAD2];
__device__ __align__(256) __nv_bfloat16 g_vocTL[(size_t)HDIM * KPAD2];
__device__ __align__(256) __nv_bfloat16 g_simH [(size_t)MROWS * KPAD2];
__device__ __align__(256) __nv_bfloat16 g_simL [(size_t)MROWS * KPAD2];

// ---------------------------------------------------------------------------
// plain-PTX helpers (sm_80+ only: cp.async, ldmatrix, mma.sync)
// ---------------------------------------------------------------------------
__device__ __forceinline__ uint32_t smem_u32(const void* p) {
    uint32_t a;
    asm("{ .reg .u64 t; cvta.to.shared.u64 t, %1; cvt.u32.u64 %0, t; }"
        : "=r"(a) : "l"(p));
    return a;
}

__device__ __forceinline__ void cp_async16(uint32_t dst, const void* src) {
    asm volatile("cp.async.cg.shared.global [%0], [%1], 16;"
                 :: "r"(dst), "l"(src));
}
__device__ __forceinline__ void cp_commit() {
    asm volatile("cp.async.commit_group;");
}
__device__ __forceinline__ void cp_wait1() {
    asm volatile("cp.async.wait_group 1;");
}

__device__ __forceinline__ void ldsm4(uint32_t* r, uint32_t addr) {
    asm volatile("ldmatrix.sync.aligned.m8n8.x4.shared.b16 {%0,%1,%2,%3}, [%4];"
                 : "=r"(r[0]), "=r"(r[1]), "=r"(r[2]), "=r"(r[3])
                 : "r"(addr));
}

__device__ __forceinline__ void mma16816(float* c, const uint32_t* a,
                                         uint32_t b0, uint32_t b1) {
    asm volatile(
        "mma.sync.aligned.m16n8k16.row.col.f32.bf16.bf16.f32 "
        "{%0,%1,%2,%3}, {%4,%5,%6,%7}, {%8,%9}, {%0,%1,%2,%3};"
        : "+f"(c[0]), "+f"(c[1]), "+f"(c[2]), "+f"(c[3])
        : "r"(a[0]), "r"(a[1]), "r"(a[2]), "r"(a[3]), "r"(b0), "r"(b1));
}

// ---------------------------------------------------------------------------
// Conversion kernels: fp32 -> bf16 hi/lo splits
// ---------------------------------------------------------------------------
__global__ __launch_bounds__(256) void k_split_desc(const float* __restrict__ D) {
    long i = (long)blockIdx.x * 256 + threadIdx.x;
    if (i >= (long)MROWS * HDIM) return;
    float x = D[i];
    __nv_bfloat16 h = __float2bfloat16(x);
    g_descH[i] = h;
    g_descL[i] = __float2bfloat16(x - __bfloat162float(h));
}

__global__ __launch_bounds__(256) void k_split_vocab(const float* __restrict__ V,
                                                     const float* __restrict__ E) {
    long i = (long)blockIdx.x * 256 + threadIdx.x;
    if (i >= (long)NPAD1 * HDIM) return;
    long row = i >> 10;
    int  col = (int)(i & 1023);
    float x;
    if (row < DV)       x = V[i];
    else if (row == DV) x = E[col];
    else                x = 0.f;
    __nv_bfloat16 h = __float2bfloat16(x);
    g_vocH[i] = h;
    g_vocL[i] = __float2bfloat16(x - __bfloat162float(h));
}

// vocabT[n][k] = vocab[k][n], bf16 hi/lo, K padded to KPAD2 with zeros
__global__ __launch_bounds__(256) void k_vocabT(const float* __restrict__ V) {
    __shared__ float t[32][33];
    int k0 = blockIdx.x * 32;
    int n0 = blockIdx.y * 32;
    #pragma unroll
    for (int r = 0; r < 32; r += 8) {
        int k = k0 + threadIdx.y + r;
        t[threadIdx.y + r][threadIdx.x] =
            (k < DV) ? V[(long)k * HDIM + n0 + threadIdx.x] : 0.f;
    }
    __syncthreads();
    #pragma unroll
    for (int r = 0; r < 32; r += 8) {
        int n = n0 + threadIdx.y + r;
        int k = k0 + threadIdx.x;
        float x = t[threadIdx.x][threadIdx.y + r];
        __nv_bfloat16 h = __float2bfloat16(x);
        g_vocTH[(long)n * KPAD2 + k] = h;
        g_vocTL[(long)n * KPAD2 + k] = __float2bfloat16(x - __bfloat162float(h));
    }
}

// ---------------------------------------------------------------------------
// Softmax: fp32 in place + bf16 hi/lo split of sim[:, 0:DV] (default slot and
// K padding zeroed in the bf16 arrays — default slot fused in GEMM2 epilogue)
// ---------------------------------------------------------------------------
__global__ __launch_bounds__(256) void softmax_rows(float* __restrict__ P) {
    const int row = blockIdx.x;
    float* p = P + (size_t)row * NP1;

    float lm = -3.402823466e+38f;
    float ls = 0.f;
    for (int i = threadIdx.x; i < NP1; i += 256) {
        float x = p[i];
        if (x > lm) { ls = ls * expf(lm - x) + 1.f; lm = x; }
        else        { ls += expf(x - lm); }
    }

    __shared__ float sm[256];
    __shared__ float ss[256];
    sm[threadIdx.x] = lm;
    ss[threadIdx.x] = ls;
    __syncthreads();
    for (int stride = 128; stride > 0; stride >>= 1) {
        if (threadIdx.x < stride) {
            float m1 = sm[threadIdx.x],          s1 = ss[threadIdx.x];
            float m2 = sm[threadIdx.x + stride], s2 = ss[threadIdx.x + stride];
            float M = fmaxf(m1, m2);
            sm[threadIdx.x] = M;
            ss[threadIdx.x] = s1 * expf(m1 - M) + s2 * expf(m2 - M);
        }
        __syncthreads();
    }
    const float M    = sm[0];
    const float rinv = 1.f / ss[0];

    __nv_bfloat16* sh = g_simH + (long)row * KPAD2;
    __nv_bfloat16* sl = g_simL + (long)row * KPAD2;
    for (int i = threadIdx.x; i < NP1; i += 256) {
        float pv = expf(p[i] - M) * rinv;
        p[i] = pv;
        if (i < DV) {
            __nv_bfloat16 h = __float2bfloat16(pv);
            sh[i] = h;
            sl[i] = __float2bfloat16(pv - __bfloat162float(h));
        }
    }
    for (int i = DV + threadIdx.x; i < KPAD2; i += 256) {
        sh[i] = __float2bfloat16(0.f);
        sl[i] = __float2bfloat16(0.f);
    }
}

// ---------------------------------------------------------------------------
// mma.sync bf16x3 GEMM:  D[128,128] f32 = A[128,K] * B[128,K]^T
// A ~ Ah+Al, B ~ Bh+Bl; accumulate Ah*Bh + Ah*Bl + Al*Bh (fp32 accum).
// 256 threads, warp grid 2(m) x 4(n), warp tile 64x32, BK=32.
// 2-stage cp.async pipeline (80KB smem) so 2 CTAs fit per SM (occupancy fix:
// Round-6 profile showed tensor=45%, occ=12.5% with the 3-stage/120KB layout).
// Smem per stage: 4 tiles (Ah,Al,Bh,Bl), 128 rows x 64B data, 80B padded row.
// MODE 0: logits epilogue (ldc=NP1, column guard)
// MODE 1: blend epilogue  (C = D + sim[:,DV]*desc, ldc=HDIM)
// ---------------------------------------------------------------------------
#define AREA  10240              // one tile (128 rows * 80B)
#define STAGE 40960              // 4 tiles
#define GEMM_SMEM_BYTES (2 * STAGE)

__device__ __forceinline__ void stage_load(
    uint32_t stb,
    const __nv_bfloat16* __restrict__ Ah, const __nv_bfloat16* __restrict__ Al,
    long bm, long lda,
    const __nv_bfloat16* __restrict__ Bh, const __nv_bfloat16* __restrict__ Bl,
    long bn, long ldb,
    int k0, int tid)
{
    const int seg = tid & 3;
    #pragma unroll
    for (int r = 0; r < 8; r++) {
        const int arr = r >> 1;                       // 0..3: Ah, Al, Bh, Bl
        const int row = (r & 1) * 64 + (tid >> 2);    // 0..127
        const __nv_bfloat16* src;
        if (arr == 0)      src = Ah + (bm + row) * lda;
        else if (arr == 1) src = Al + (bm + row) * lda;
        else if (arr == 2) src = Bh + (bn + row) * ldb;
        else               src = Bl + (bn + row) * ldb;
        src += k0 + seg * 8;
        uint32_t dst = stb + (uint32_t)arr * AREA + (uint32_t)row * 80 + (uint32_t)seg * 16;
        cp_async16(dst, src);
    }
}

template <int MODE>
__global__ __launch_bounds__(256, 2)
void gemm_bf16x3(const __nv_bfloat16* __restrict__ Ah,
                 const __nv_bfloat16* __restrict__ Al, long lda,
                 const __nv_bfloat16* __restrict__ Bh,
                 const __nv_bfloat16* __restrict__ Bl, long ldb,
                 int KTOT,
                 float* __restrict__ C,
                 const float* __restrict__ simF,
                 const float* __restrict__ descF)
{
    extern __shared__ char smem[];
    const int tid  = threadIdx.x;
    const int lane = tid & 31;
    const int wid  = tid >> 5;
    const int wm   = wid >> 2;      // 0..1
    const int wn   = wid & 3;       // 0..3
    const uint32_t sb = smem_u32(smem);

    const long bm = (long)blockIdx.y * 128;
    const long bn = (long)blockIdx.x * 128;

    // ldmatrix per-lane addressing: tiles ordered (r0,k0),(r8,k0),(r0,k8),(r8,k8)
    const int lrow = ((lane >> 3) & 1) * 8 + (lane & 7);
    const int lseg = lane >> 4;     // 0..1 (16B column segment within k16)

    float acc[4][4][4];
    #pragma unroll
    for (int i = 0; i < 4; i++)
        #pragma unroll
        for (int j = 0; j < 4; j++)
            #pragma unroll
            for (int q = 0; q < 4; q++) acc[i][j][q] = 0.f;

    const int NC = KTOT >> 5;

    // 2-stage pipeline:
    //   prologue: load s0, commit.
    //   iter c:   issue loads for c+1 into the other buffer, commit,
    //             wait_group 1 (-> stage c resident), sync, compute c, sync.
    // The trailing sync of iter c guarantees buffer cs is fully consumed
    // before iter c+1 overwrites it.
    stage_load(sb, Ah, Al, bm, lda, Bh, Bl, bn, ldb, 0, tid);
    cp_commit();

    uint32_t cs = 0;  // current stage (0/1)
    for (int c = 0; c < NC; ++c) {
        if (c + 1 < NC)
            stage_load(sb + (cs ^ 1u) * STAGE, Ah, Al, bm, lda, Bh, Bl, bn, ldb,
                       (c + 1) << 5, tid);
        cp_commit();
        cp_wait1();
        __syncthreads();

        const uint32_t stb = sb + cs * STAGE;
        #pragma unroll
        for (int kh = 0; kh < 2; kh++) {
            uint32_t afH[4][4], afL[4][4];
            #pragma unroll
            for (int mt = 0; mt < 4; mt++) {
                uint32_t ra = stb + (uint32_t)((wm * 64 + mt * 16 + lrow) * 80
                                               + kh * 32 + lseg * 16);
                ldsm4(afH[mt], ra);
                ldsm4(afL[mt], ra + AREA);
            }
            uint32_t bfH[2][4], bfL[2][4];
            #pragma unroll
            for (int nt = 0; nt < 2; nt++) {
                uint32_t rb = stb + 2u * AREA
                            + (uint32_t)((wn * 32 + nt * 16 + lrow) * 80
                                         + kh * 32 + lseg * 16);
                ldsm4(bfH[nt], rb);
                ldsm4(bfL[nt], rb + AREA);
            }
            #pragma unroll
            for (int mt = 0; mt < 4; mt++) {
                #pragma unroll
                for (int nb = 0; nb < 4; nb++) {
                    const int nt = nb >> 1, hs = nb & 1;
                    mma16816(acc[mt][nb], afH[mt], bfH[nt][hs], bfH[nt][hs + 2]);
                    mma16816(acc[mt][nb], afH[mt], bfL[nt][hs], bfL[nt][hs + 2]);
                    mma16816(acc[mt][nb], afL[mt], bfH[nt][hs], bfH[nt][hs + 2]);
                }
            }
        }
        __syncthreads();
        cs ^= 1u;
    }

    // ---- epilogue: direct stores from mma C fragments
    const int group = lane >> 2;
    const int q2    = (lane & 3) * 2;
    #pragma unroll
    for (int mt = 0; mt < 4; mt++) {
        long m0 = bm + wm * 64 + mt * 16 + group;
        long m1 = m0 + 8;
        float w0 = 0.f, w1 = 0.f;
        if (MODE == 1) {
            w0 = simF[m0 * NP1 + DV];
            w1 = simF[m1 * NP1 + DV];
        }
        #pragma unroll
        for (int nb = 0; nb < 4; nb++) {
            long n = bn + wn * 32 + nb * 8 + q2;
            const float* cc = acc[mt][nb];
            if (MODE == 0) {
                if (n < NP1)     C[m0 * NP1 + n]     = cc[0];
                if (n + 1 < NP1) C[m0 * NP1 + n + 1] = cc[1];
                if (n < NP1)     C[m1 * NP1 + n]     = cc[2];
                if (n + 1 < NP1) C[m1 * NP1 + n + 1] = cc[3];
            } else {
                C[m0 * HDIM + n]     = cc[0] + w0 * descF[m0 * HDIM + n];
                C[m0 * HDIM + n + 1] = cc[1] + w0 * descF[m0 * HDIM + n + 1];
                C[m1 * HDIM + n]     = cc[2] + w1 * descF[m1 * HDIM + n];
                C[m1 * HDIM + n + 1] = cc[3] + w1 * descF[m1 * HDIM + n + 1];
            }
        }
    }
}

// ---------------------------------------------------------------------------
extern "C" void kernel_launch(void* const* d_in, const int* in_sizes, int n_in,
                              void* d_out, int out_size)
{
    const float* vocab = (const float*)d_in[0];   // 10000 x 1024
    const float* desc  = (const float*)d_in[1];   // 8 x 512 x 1024
    const float* defe  = (const float*)d_in[2];   // 1024

    float* concept = (float*)d_out;                       // 4096 x 1024
    float* sim     = concept + (size_t)MROWS * HDIM;      // 4096 x 10001

    // Real device addresses of the __device__ scratch symbols (Round-5 fix:
    // passing the symbols directly gives the host shadow, which ATS serves
    // as zeros on GB300).
    __nv_bfloat16 *descH, *descL, *vocH, *vocL, *vocTH, *vocTL, *simH, *simL;
    cudaGetSymbolAddress((void**)&descH, g_descH);
    cudaGetSymbolAddress((void**)&descL, g_descL);
    cudaGetSymbolAddress((void**)&vocH,  g_vocH);
    cudaGetSymbolAddress((void**)&vocL,  g_vocL);
    cudaGetSymbolAddress((void**)&vocTH, g_vocTH);
    cudaGetSymbolAddress((void**)&vocTL, g_vocTL);
    cudaGetSymbolAddress((void**)&simH,  g_simH);
    cudaGetSymbolAddress((void**)&simL,  g_simL);

    cudaFuncSetAttribute(gemm_bf16x3<0>, cudaFuncAttributeMaxDynamicSharedMemorySize,
                         GEMM_SMEM_BYTES);
    cudaFuncSetAttribute(gemm_bf16x3<1>, cudaFuncAttributeMaxDynamicSharedMemorySize,
                         GEMM_SMEM_BYTES);

    // 0) fp32 -> bf16 hi/lo conversions
    {
        long n1 = (long)MROWS * HDIM;
        k_split_desc<<<(unsigned)((n1 + 255) / 256), 256>>>(desc);
        long n2 = (long)NPAD1 * HDIM;
        k_split_vocab<<<(unsigned)((n2 + 255) / 256), 256>>>(vocab, defe);
        dim3 tg(KPAD2 / 32, HDIM / 32);
        k_vocabT<<<tg, dim3(32, 8)>>>(vocab);
    }
    // 1) logits = desc @ fullvocab^T  -> sim region (fp32)
    {
        dim3 grid(NPAD1 / 128, MROWS / 128);   // 79 x 32
        gemm_bf16x3<0><<<grid, 256, GEMM_SMEM_BYTES>>>(
            descH, descL, HDIM,
            vocH,  vocL,  HDIM,
            HDIM, sim, nullptr, nullptr);
    }
    // 2) softmax in place + bf16 hi/lo sim
    softmax_rows<<<MROWS, 256>>>(sim);
    // 3) concept = sim[:, :DV] @ vocab + sim[:, DV] * desc
    {
        dim3 grid(HDIM / 128, MROWS / 128);    // 8 x 32
        gemm_bf16x3<1><<<grid, 256, GEMM_SMEM_BYTES>>>(
            simH,  simL,  KPAD2,
            vocTH, vocTL, KPAD2,
            KPAD2, concept, sim, desc);
    }
}

// round 8
// speedup vs baseline: 2.7356x; 1.0346x over previous
#include <cuda_runtime.h>
#include <cuda_bf16.h>
#include <stdint.h>
#include <math.h>

#define DV    10000      // vocab rows
#define NP1   10001      // D+1 (softmax width)
#define HDIM  1024       // hidden
#define MROWS 4096       // B*L
#define NPAD1 10112      // 79*128   (GEMM1 N padding, vocab rows)
#define KPAD2 10048      // 314*32   (GEMM2 K padding)

// ---------------------------------------------------------------------------
// Static device scratch (allocation-free rule: __device__ globals)
// NOTE: host code must use cudaGetSymbolAddress — passing these identifiers
// directly as kernel args from host yields the host shadow (Round-5 bug).
// ---------------------------------------------------------------------------
__device__ __align__(256) __nv_bfloat16 g_descH[(size_t)MROWS * HDIM];
__device__ __align__(256) __nv_bfloat16 g_descL[(size_t)MROWS * HDIM];
__device__ __align__(256) __nv_bfloat16 g_vocH [(size_t)NPAD1 * HDIM];
__device__ __align__(256) __nv_bfloat16 g_vocL [(size_t)NPAD1 * HDIM];
__device__ __align__(256) __nv_bfloat16 g_vocTH[(size_t)HDIM * KPAD2];
__device__ __align__(256) __nv_bfloat16 g_vocTL[(size_t)HDIM * KPAD2];
__device__ __align__(256) __nv_bfloat16 g_simH [(size_t)MROWS * KPAD2];
__device__ __align__(256) __nv_bfloat16 g_simL [(size_t)MROWS * KPAD2];

// ---------------------------------------------------------------------------
// plain-PTX helpers (sm_80+ only: cp.async, ldmatrix, mma.sync)
// ---------------------------------------------------------------------------
__device__ __forceinline__ uint32_t smem_u32(const void* p) {
    uint32_t a;
    asm("{ .reg .u64 t; cvta.to.shared.u64 t, %1; cvt.u32.u64 %0, t; }"
        : "=r"(a) : "l"(p));
    return a;
}

__device__ __forceinline__ void cp_async16(uint32_t dst, const void* src) {
    asm volatile("cp.async.cg.shared.global [%0], [%1], 16;"
                 :: "r"(dst), "l"(src));
}
__device__ __forceinline__ void cp_commit() {
    asm volatile("cp.async.commit_group;");
}
__device__ __forceinline__ void cp_wait1() {
    asm volatile("cp.async.wait_group 1;");
}

__device__ __forceinline__ void ldsm4(uint32_t* r, uint32_t addr) {
    asm volatile("ldmatrix.sync.aligned.m8n8.x4.shared.b16 {%0,%1,%2,%3}, [%4];"
                 : "=r"(r[0]), "=r"(r[1]), "=r"(r[2]), "=r"(r[3])
                 : "r"(addr));
}

__device__ __forceinline__ void mma16816(float* c, const uint32_t* a,
                                         uint32_t b0, uint32_t b1) {
    asm volatile(
        "mma.sync.aligned.m16n8k16.row.col.f32.bf16.bf16.f32 "
        "{%0,%1,%2,%3}, {%4,%5,%6,%7}, {%8,%9}, {%0,%1,%2,%3};"
        : "+f"(c[0]), "+f"(c[1]), "+f"(c[2]), "+f"(c[3])
        : "r"(a[0]), "r"(a[1]), "r"(a[2]), "r"(a[3]), "r"(b0), "r"(b1));
}

// Swizzled tile layout: logical (row 0..127, seg 0..3 of 16B) within an
// 8KB tile (64B of data per row).  Physical: rows paired into 128B blocks;
// chunk index i' = ((row&1)*4 + seg) ^ ((row>>1)&7).  Conflict-free for
// both the 4-thread/row cp.async stores and 8-row ldmatrix phases.
__device__ __forceinline__ uint32_t swz(int row, int seg) {
    return (uint32_t)(((row >> 1) << 7)
                      + (((((row & 1) << 2) + seg) ^ ((row >> 1) & 7)) << 4));
}

// ---------------------------------------------------------------------------
// Conversion kernels: fp32 -> bf16 hi/lo splits
// ---------------------------------------------------------------------------
__global__ __launch_bounds__(256) void k_split_desc(const float* __restrict__ D) {
    long i = (long)blockIdx.x * 256 + threadIdx.x;
    if (i >= (long)MROWS * HDIM) return;
    float x = D[i];
    __nv_bfloat16 h = __float2bfloat16(x);
    g_descH[i] = h;
    g_descL[i] = __float2bfloat16(x - __bfloat162float(h));
}

__global__ __launch_bounds__(256) void k_split_vocab(const float* __restrict__ V,
                                                     const float* __restrict__ E) {
    long i = (long)blockIdx.x * 256 + threadIdx.x;
    if (i >= (long)NPAD1 * HDIM) return;
    long row = i >> 10;
    int  col = (int)(i & 1023);
    float x;
    if (row < DV)       x = V[i];
    else if (row == DV) x = E[col];
    else                x = 0.f;
    __nv_bfloat16 h = __float2bfloat16(x);
    g_vocH[i] = h;
    g_vocL[i] = __float2bfloat16(x - __bfloat162float(h));
}

// vocabT[n][k] = vocab[k][n], bf16 hi/lo, K padded to KPAD2 with zeros
__global__ __launch_bounds__(256) void k_vocabT(const float* __restrict__ V) {
    __shared__ float t[32][33];
    int k0 = blockIdx.x * 32;
    int n0 = blockIdx.y * 32;
    #pragma unroll
    for (int r = 0; r < 32; r += 8) {
        int k = k0 + threadIdx.y + r;
        t[threadIdx.y + r][threadIdx.x] =
            (k < DV) ? V[(long)k * HDIM + n0 + threadIdx.x] : 0.f;
    }
    __syncthreads();
    #pragma unroll
    for (int r = 0; r < 32; r += 8) {
        int n = n0 + threadIdx.y + r;
        int k = k0 + threadIdx.x;
        float x = t[threadIdx.x][threadIdx.y + r];
        __nv_bfloat16 h = __float2bfloat16(x);
        g_vocTH[(long)n * KPAD2 + k] = h;
        g_vocTL[(long)n * KPAD2 + k] = __float2bfloat16(x - __bfloat162float(h));
    }
}

// ---------------------------------------------------------------------------
// Softmax: single global read pass (row cached in 40 registers), fp32 written
// in place + bf16 hi/lo split of sim[:, 0:DV] (default slot and K padding
// zeroed in the bf16 arrays — default slot fused in GEMM2 epilogue)
// ---------------------------------------------------------------------------
#define SM_ITER 40      // ceil(NP1 / 256)

__global__ __launch_bounds__(256) void softmax_rows(float* __restrict__ P) {
    const int row = blockIdx.x;
    const int tid = threadIdx.x;
    float* p = P + (size_t)row * NP1;

    float v[SM_ITER];
    float lm = -3.402823466e+38f;
    #pragma unroll
    for (int c = 0; c < SM_ITER; c++) {
        int i = tid + c * 256;
        v[c] = (i < NP1) ? p[i] : -3.402823466e+38f;
        lm = fmaxf(lm, v[c]);
    }

    __shared__ float sm[256];
    __shared__ float ss[256];
    sm[tid] = lm;
    __syncthreads();
    for (int stride = 128; stride > 0; stride >>= 1) {
        if (tid < stride) sm[tid] = fmaxf(sm[tid], sm[tid + stride]);
        __syncthreads();
    }
    const float M = sm[0];

    float ls = 0.f;
    #pragma unroll
    for (int c = 0; c < SM_ITER; c++) {
        v[c] = expf(v[c] - M);     // exp(-inf) = 0 for padding lanes
        ls += v[c];
    }
    ss[tid] = ls;
    __syncthreads();
    for (int stride = 128; stride > 0; stride >>= 1) {
        if (tid < stride) ss[tid] += ss[tid + stride];
        __syncthreads();
    }
    const float rinv = 1.f / ss[0];

    __nv_bfloat16* sh = g_simH + (long)row * KPAD2;
    __nv_bfloat16* sl = g_simL + (long)row * KPAD2;
    #pragma unroll
    for (int c = 0; c < SM_ITER; c++) {
        int i = tid + c * 256;
        if (i < NP1) {
            float pv = v[c] * rinv;
            p[i] = pv;
            if (i < DV) {
                __nv_bfloat16 h = __float2bfloat16(pv);
                sh[i] = h;
                sl[i] = __float2bfloat16(pv - __bfloat162float(h));
            }
        }
    }
    for (int i = DV + tid; i < KPAD2; i += 256) {
        sh[i] = __float2bfloat16(0.f);
        sl[i] = __float2bfloat16(0.f);
    }
}

// ---------------------------------------------------------------------------
// mma.sync bf16x3 GEMM:  D[128,128] f32 = A[128,K] * B[128,K]^T
// A ~ Ah+Al, B ~ Bh+Bl; accumulate Ah*Bh + Ah*Bl + Al*Bh (fp32 accum).
// 256 threads, warp grid 2(m) x 4(n), warp tile 64x32, BK=32.
// 3-stage cp.async pipeline, ONE __syncthreads per chunk (multistage order:
// wait -> barrier -> issue loads for c+2 -> compute c).  Swizzled 8KB tiles
// (no padding) keep a stage at 32KB -> 96KB total -> 2 CTAs/SM.
// All global pointers and ldmatrix smem offsets are hoisted out of the loop
// (Round-7 profile: 22% of issue was IMAD/ALU addressing).
// MODE 0: logits epilogue (ldc=NP1, column guard)
// MODE 1: blend epilogue  (C = D + sim[:,DV]*desc, ldc=HDIM)
// ---------------------------------------------------------------------------
#define TILE  8192               // one tile (128 rows * 64B, swizzled)
#define STAGE 32768              // 4 tiles (Ah, Al, Bh, Bl)
#define GEMM_SMEM_BYTES (3 * STAGE)

template <int MODE>
__global__ __launch_bounds__(256, 2)
void gemm_bf16x3(const __nv_bfloat16* __restrict__ Ah,
                 const __nv_bfloat16* __restrict__ Al, long lda,
                 const __nv_bfloat16* __restrict__ Bh,
                 const __nv_bfloat16* __restrict__ Bl, long ldb,
                 int KTOT,
                 float* __restrict__ C,
                 const float* __restrict__ simF,
                 const float* __restrict__ descF)
{
    extern __shared__ char smem[];
    const int tid  = threadIdx.x;
    const int lane = tid & 31;
    const int wid  = tid >> 5;
    const int wm   = wid >> 2;      // 0..1
    const int wn   = wid & 3;       // 0..3
    const uint32_t sb = smem_u32(smem);

    const long bm = (long)blockIdx.y * 128;
    const long bn = (long)blockIdx.x * 128;

    // ---- loader assignment: row = tid>>1, segs {2*(tid&1), 2*(tid&1)+1}
    const int lr   = tid >> 1;            // 0..127
    const int lsg0 = (tid & 1) * 2;       // 0 or 2
    const uint32_t d0 = swz(lr, lsg0);          // dst offsets within a tile
    const uint32_t d1 = swz(lr, lsg0 + 1);

    // persistent global pointers, advanced 32 elems (64B) per chunk
    const __nv_bfloat16* pAh = Ah + (bm + lr) * lda + lsg0 * 8;
    const __nv_bfloat16* pAl = Al + (bm + lr) * lda + lsg0 * 8;
    const __nv_bfloat16* pBh = Bh + (bn + lr) * ldb + lsg0 * 8;
    const __nv_bfloat16* pBl = Bl + (bn + lr) * ldb + lsg0 * 8;

    // ---- ldmatrix lane addressing (loop-invariant swizzled offsets)
    const int lrow = ((lane >> 3) & 1) * 8 + (lane & 7);
    const int lseg = lane >> 4;           // 0..1 (16B segment within k16)
    uint32_t swzA[4][2], swzB[2][2];
    #pragma unroll
    for (int mt = 0; mt < 4; mt++)
        #pragma unroll
        for (int kh = 0; kh < 2; kh++)
            swzA[mt][kh] = swz(wm * 64 + mt * 16 + lrow, kh * 2 + lseg);
    #pragma unroll
    for (int nt = 0; nt < 2; nt++)
        #pragma unroll
        for (int kh = 0; kh < 2; kh++)
            swzB[nt][kh] = swz(wn * 32 + nt * 16 + lrow, kh * 2 + lseg);

    float acc[4][4][4];
    #pragma unroll
    for (int i = 0; i < 4; i++)
        #pragma unroll
        for (int j = 0; j < 4; j++)
            #pragma unroll
            for (int q = 0; q < 4; q++) acc[i][j][q] = 0.f;

    const int NC = KTOT >> 5;

    // one stage = Ah | Al | Bh | Bl tiles at +0, +TILE, +2*TILE, +3*TILE
    #define ISSUE_STAGE(SOFF)                                            \
        do {                                                             \
            uint32_t _b = sb + (SOFF);                                   \
            cp_async16(_b + d0,            pAh);                         \
            cp_async16(_b + d1,            pAh + 8);                     \
            cp_async16(_b + TILE + d0,     pAl);                         \
            cp_async16(_b + TILE + d1,     pAl + 8);                     \
            cp_async16(_b + 2*TILE + d0,   pBh);                         \
            cp_async16(_b + 2*TILE + d1,   pBh + 8);                     \
            cp_async16(_b + 3*TILE + d0,   pBl);                         \
            cp_async16(_b + 3*TILE + d1,   pBl + 8);                     \
            pAh += 32; pAl += 32; pBh += 32; pBl += 32;                  \
        } while (0)

    // prologue: stages 0 and 1 in flight
    ISSUE_STAGE(0);
    cp_commit();
    ISSUE_STAGE(STAGE);
    cp_commit();

    uint32_t soff = 0;                    // byte offset of current stage
    for (int c = 0; c < NC; ++c) {
        cp_wait1();                       // group c complete (<=1 outstanding)
        __syncthreads();                  // publish stage c; buffer c+2 free

        if (c + 2 < NC) {
            uint32_t noff = soff + 2u * STAGE;
            if (noff >= 3u * STAGE) noff -= 3u * STAGE;
            ISSUE_STAGE(noff);
        }
        cp_commit();                      // unconditional: keep group count

        const uint32_t stb = sb + soff;
        #pragma unroll
        for (int kh = 0; kh < 2; kh++) {
            uint32_t afH[4][4], afL[4][4];
            #pragma unroll
            for (int mt = 0; mt < 4; mt++) {
                uint32_t ra = stb + swzA[mt][kh];
                ldsm4(afH[mt], ra);
                ldsm4(afL[mt], ra + TILE);
            }
            uint32_t bfH[2][4], bfL[2][4];
            #pragma unroll
            for (int nt = 0; nt < 2; nt++) {
                uint32_t rb = stb + 2u * TILE + swzB[nt][kh];
                ldsm4(bfH[nt], rb);
                ldsm4(bfL[nt], rb + TILE);
            }
            #pragma unroll
            for (int mt = 0; mt < 4; mt++) {
                #pragma unroll
                for (int nb = 0; nb < 4; nb++) {
                    const int nt = nb >> 1, hs = nb & 1;
                    mma16816(acc[mt][nb], afH[mt], bfH[nt][hs], bfH[nt][hs + 2]);
                    mma16816(acc[mt][nb], afH[mt], bfL[nt][hs], bfL[nt][hs + 2]);
                    mma16816(acc[mt][nb], afL[mt], bfH[nt][hs], bfH[nt][hs + 2]);
                }
            }
        }
        soff += STAGE;
        if (soff >= 3u * STAGE) soff -= 3u * STAGE;
    }
    #undef ISSUE_STAGE

    // ---- epilogue: direct stores from mma C fragments
    const int group = lane >> 2;
    const int q2    = (lane & 3) * 2;
    #pragma unroll
    for (int mt = 0; mt < 4; mt++) {
        long m0 = bm + wm * 64 + mt * 16 + group;
        long m1 = m0 + 8;
        float w0 = 0.f, w1 = 0.f;
        if (MODE == 1) {
            w0 = simF[m0 * NP1 + DV];
            w1 = simF[m1 * NP1 + DV];
        }
        #pragma unroll
        for (int nb = 0; nb < 4; nb++) {
            long n = bn + wn * 32 + nb * 8 + q2;
            const float* cc = acc[mt][nb];
            if (MODE == 0) {
                if (n < NP1)     C[m0 * NP1 + n]     = cc[0];
                if (n + 1 < NP1) C[m0 * NP1 + n + 1] = cc[1];
                if (n < NP1)     C[m1 * NP1 + n]     = cc[2];
                if (n + 1 < NP1) C[m1 * NP1 + n + 1] = cc[3];
            } else {
                C[m0 * HDIM + n]     = cc[0] + w0 * descF[m0 * HDIM + n];
                C[m0 * HDIM + n + 1] = cc[1] + w0 * descF[m0 * HDIM + n + 1];
                C[m1 * HDIM + n]     = cc[2] + w1 * descF[m1 * HDIM + n];
                C[m1 * HDIM + n + 1] = cc[3] + w1 * descF[m1 * HDIM + n + 1];
            }
        }
    }
}

// ---------------------------------------------------------------------------
extern "C" void kernel_launch(void* const* d_in, const int* in_sizes, int n_in,
                              void* d_out, int out_size)
{
    const float* vocab = (const float*)d_in[0];   // 10000 x 1024
    const float* desc  = (const float*)d_in[1];   // 8 x 512 x 1024
    const float* defe  = (const float*)d_in[2];   // 1024

    float* concept = (float*)d_out;                       // 4096 x 1024
    float* sim     = concept + (size_t)MROWS * HDIM;      // 4096 x 10001

    // Real device addresses of the __device__ scratch symbols (Round-5 fix:
    // passing the symbols directly gives the host shadow, which ATS serves
    // as zeros on GB300).
    __nv_bfloat16 *descH, *descL, *vocH, *vocL, *vocTH, *vocTL, *simH, *simL;
    cudaGetSymbolAddress((void**)&descH, g_descH);
    cudaGetSymbolAddress((void**)&descL, g_descL);
    cudaGetSymbolAddress((void**)&vocH,  g_vocH);
    cudaGetSymbolAddress((void**)&vocL,  g_vocL);
    cudaGetSymbolAddress((void**)&vocTH, g_vocTH);
    cudaGetSymbolAddress((void**)&vocTL, g_vocTL);
    cudaGetSymbolAddress((void**)&simH,  g_simH);
    cudaGetSymbolAddress((void**)&simL,  g_simL);

    cudaFuncSetAttribute(gemm_bf16x3<0>, cudaFuncAttributeMaxDynamicSharedMemorySize,
                         GEMM_SMEM_BYTES);
    cudaFuncSetAttribute(gemm_bf16x3<1>, cudaFuncAttributeMaxDynamicSharedMemorySize,
                         GEMM_SMEM_BYTES);

    // 0) fp32 -> bf16 hi/lo conversions
    {
        long n1 = (long)MROWS * HDIM;
        k_split_desc<<<(unsigned)((n1 + 255) / 256), 256>>>(desc);
        long n2 = (long)NPAD1 * HDIM;
        k_split_vocab<<<(unsigned)((n2 + 255) / 256), 256>>>(vocab, defe);
        dim3 tg(KPAD2 / 32, HDIM / 32);
        k_vocabT<<<tg, dim3(32, 8)>>>(vocab);
    }
    // 1) logits = desc @ fullvocab^T  -> sim region (fp32)
    {
        dim3 grid(NPAD1 / 128, MROWS / 128);   // 79 x 32
        gemm_bf16x3<0><<<grid, 256, GEMM_SMEM_BYTES>>>(
            descH, descL, HDIM,
            vocH,  vocL,  HDIM,
            HDIM, sim, nullptr, nullptr);
    }
    // 2) softmax in place (one-pass) + bf16 hi/lo sim
    softmax_rows<<<MROWS, 256>>>(sim);
    // 3) concept = sim[:, :DV] @ vocab + sim[:, DV] * desc
    {
        dim3 grid(HDIM / 128, MROWS / 128);    // 8 x 32
        gemm_bf16x3<1><<<grid, 256, GEMM_SMEM_BYTES>>>(
            simH,  simL,  KPAD2,
            vocTH, vocTL, KPAD2,
            KPAD2, concept, sim, desc);
    }
}